// round 1
// baseline (speedup 1.0000x reference)
#include <cuda_runtime.h>
#include <math.h>

#define NROWS 8192
#define DDIM  64
#define TI    128
#define TJ    128
#define KC    32

// Scratch (no allocations allowed -> __device__ globals)
__device__ float g_ET[DDIM][NROWS];   // transposed encoded, 2 MB
__device__ float g_sq[NROWS];
__device__ float g_rowsum[NROWS];
__device__ float g_mse;

__global__ void init_kernel() {
    int i = blockIdx.x * blockDim.x + threadIdx.x;
    if (i < NROWS) g_rowsum[i] = 0.0f;
    if (i == 0)    g_mse = 0.0f;
}

// Transpose encoded into g_ET and compute per-row squared norms.
// Threads = rows; stores ET[d][i] are coalesced across the warp (consecutive i).
__global__ void prep_kernel(const float* __restrict__ E) {
    int i = blockIdx.x * blockDim.x + threadIdx.x;
    if (i >= NROWS) return;
    const float4* row = reinterpret_cast<const float4*>(E + (size_t)i * DDIM);
    float s = 0.0f;
#pragma unroll
    for (int q = 0; q < DDIM / 4; q++) {
        float4 v = row[q];
        s += v.x * v.x + v.y * v.y + v.z * v.z + v.w * v.w;
        g_ET[4 * q + 0][i] = v.x;
        g_ET[4 * q + 1][i] = v.y;
        g_ET[4 * q + 2][i] = v.z;
        g_ET[4 * q + 3][i] = v.w;
    }
    g_sq[i] = s;
}

// One 128x128 tile of the Gram matrix per block; fused exp + row-sum epilogue.
__global__ void __launch_bounds__(256, 2) gram_kernel() {
    __shared__ float As[KC][TI];
    __shared__ float Bs[KC][TJ];
    const int i0 = blockIdx.y * TI;
    const int j0 = blockIdx.x * TJ;
    const int tid = threadIdx.x;
    const int tx = tid & 15;
    const int ty = tid >> 4;
    const int ri = ty * 8;
    const int rj = tx * 8;

    float acc[8][8];
#pragma unroll
    for (int r = 0; r < 8; r++)
#pragma unroll
        for (int c = 0; c < 8; c++) acc[r][c] = 0.0f;

    for (int kk = 0; kk < DDIM; kk += KC) {
        // Load KC x 128 chunks of both tiles: 1024 float4 per matrix, 4 per thread.
#pragma unroll
        for (int l = 0; l < 4; l++) {
            int idx = tid + 256 * l;        // 0..1023
            int k   = idx >> 5;             // 0..31
            int c4  = (idx & 31) << 2;      // 0,4,...,124
            *reinterpret_cast<float4*>(&As[k][c4]) =
                *reinterpret_cast<const float4*>(&g_ET[kk + k][i0 + c4]);
            *reinterpret_cast<float4*>(&Bs[k][c4]) =
                *reinterpret_cast<const float4*>(&g_ET[kk + k][j0 + c4]);
        }
        __syncthreads();
#pragma unroll 8
        for (int k = 0; k < KC; k++) {
            float a[8], b[8];
            *reinterpret_cast<float4*>(&a[0]) = *reinterpret_cast<float4*>(&As[k][ri]);
            *reinterpret_cast<float4*>(&a[4]) = *reinterpret_cast<float4*>(&As[k][ri + 4]);
            *reinterpret_cast<float4*>(&b[0]) = *reinterpret_cast<float4*>(&Bs[k][rj]);
            *reinterpret_cast<float4*>(&b[4]) = *reinterpret_cast<float4*>(&Bs[k][rj + 4]);
#pragma unroll
            for (int r = 0; r < 8; r++)
#pragma unroll
                for (int c = 0; c < 8; c++)
                    acc[r][c] = fmaf(a[r], b[c], acc[r][c]);
        }
        __syncthreads();
    }

    float sqi[8], sqj[8];
#pragma unroll
    for (int r = 0; r < 8; r++) sqi[r] = g_sq[i0 + ri + r];
#pragma unroll
    for (int c = 0; c < 8; c++) sqj[c] = g_sq[j0 + rj + c];

    // -0.5*d2 = min(0, dot - 0.5*(sq_i + sq_j))  (VAR = 1)
    float rs[8];
#pragma unroll
    for (int r = 0; r < 8; r++) {
        float s = 0.0f;
#pragma unroll
        for (int c = 0; c < 8; c++) {
            float arg = fminf(acc[r][c] - 0.5f * (sqi[r] + sqj[c]), 0.0f);
            s += __expf(arg);
        }
        rs[r] = s;
    }

    // Reduce the 16 column-partials per row inside the block, then one atomic per row.
    float* red = &As[0][0];   // 128 * 16 = 2048 floats, fits in As
    __syncthreads();
#pragma unroll
    for (int r = 0; r < 8; r++) red[(ri + r) * 16 + tx] = rs[r];
    __syncthreads();
    if (tid < TI) {
        float s = 0.0f;
#pragma unroll
        for (int t = 0; t < 16; t++) s += red[tid * 16 + t];
        atomicAdd(&g_rowsum[i0 + tid], s);
    }
}

__global__ void mse_kernel(const float* __restrict__ yt, const float* __restrict__ yp) {
    int idx = blockIdx.x * blockDim.x + threadIdx.x;   // 131072 threads, one float4 each
    float4 t = reinterpret_cast<const float4*>(yt)[idx];
    float4 p = reinterpret_cast<const float4*>(yp)[idx];
    float dx = p.x - t.x, dy = p.y - t.y, dz = p.z - t.z, dw = p.w - t.w;
    float s = dx * dx + dy * dy + dz * dz + dw * dw;
#pragma unroll
    for (int o = 16; o > 0; o >>= 1) s += __shfl_down_sync(0xffffffffu, s, o);
    if ((threadIdx.x & 31) == 0) atomicAdd(&g_mse, s);
}

__global__ void final_kernel(float* __restrict__ out) {
    __shared__ float sh[256];
    float s = 0.0f;
    for (int i = threadIdx.x; i < NROWS; i += 256) s += logf(g_rowsum[i]);
    sh[threadIdx.x] = s;
    __syncthreads();
    for (int o = 128; o > 0; o >>= 1) {
        if (threadIdx.x < o) sh[threadIdx.x] += sh[threadIdx.x + o];
        __syncthreads();
    }
    if (threadIdx.x == 0) {
        float kde  = sh[0] / (float)NROWS;                      // mean logsumexp (nats)
        float IXT  = (logf((float)NROWS) - kde) * 1.44269504088896340736f; // / ln 2
        float dist = g_mse / (float)(NROWS * DDIM);
        out[0] = IXT + 500.0f * dist;   // ALPHA*IXT + BETA*distortion
        out[1] = IXT;
        out[2] = dist;
    }
}

extern "C" void kernel_launch(void* const* d_in, const int* in_sizes, int n_in,
                              void* d_out, int out_size) {
    const float* y_true  = (const float*)d_in[0];
    const float* y_pred  = (const float*)d_in[1];
    const float* encoded = (const float*)d_in[2];
    float* out = (float*)d_out;

    init_kernel<<<(NROWS + 255) / 256, 256>>>();
    prep_kernel<<<(NROWS + 255) / 256, 256>>>(encoded);
    mse_kernel<<<(NROWS * DDIM / 4) / 256, 256>>>(y_true, y_pred);
    gram_kernel<<<dim3(NROWS / TJ, NROWS / TI), 256>>>();
    final_kernel<<<1, 256>>>(out);
}

// round 3
// speedup vs baseline: 3.1633x; 3.1633x over previous
#include <cuda_runtime.h>
#include <cuda_bf16.h>
#include <cstdint>
#include <math.h>

#define NROWS 8192
#define DDIM  64
#define NTILE (NROWS / 128)     // 64 i-tiles
#define JCHUNK 8                // j-tiles per CTA -> grid 64 x 8

// ---------------- scratch (__device__ globals; no allocations allowed) ----
__device__ __align__(16) __nv_bfloat16 g_Ebf[NROWS][DDIM];  // 1 MB
__device__ float g_sq[NROWS];
__device__ float g_rowsum[NROWS];
__device__ float g_mse;

__device__ __forceinline__ uint32_t smem_u32(const void* p) {
    uint32_t a;
    asm("{ .reg .u64 t; cvta.to.shared.u64 t, %1; cvt.u32.u64 %0, t; }"
        : "=r"(a) : "l"(p));
    return a;
}
__device__ __forceinline__ void ldsm_x4(uint32_t* r, uint32_t addr) {
    asm volatile("ldmatrix.sync.aligned.m8n8.x4.shared.b16 {%0,%1,%2,%3}, [%4];"
                 : "=r"(r[0]), "=r"(r[1]), "=r"(r[2]), "=r"(r[3]) : "r"(addr));
}
__device__ __forceinline__ void mma_bf16(float* d, const uint32_t* a,
                                         const uint32_t* b) {
    asm volatile(
        "mma.sync.aligned.m16n8k16.row.col.f32.bf16.bf16.f32 "
        "{%0,%1,%2,%3}, {%4,%5,%6,%7}, {%8,%9}, {%0,%1,%2,%3};"
        : "+f"(d[0]), "+f"(d[1]), "+f"(d[2]), "+f"(d[3])
        : "r"(a[0]), "r"(a[1]), "r"(a[2]), "r"(a[3]), "r"(b[0]), "r"(b[1]));
}

// ---------------- kernels -------------------------------------------------
__global__ void init_kernel() {
    int i = blockIdx.x * blockDim.x + threadIdx.x;
    if (i < NROWS) g_rowsum[i] = 0.0f;
    if (i == 0)    g_mse = 0.0f;
}

// fp32 -> bf16 quantize + squared norms computed from the SAME bf16 values
__global__ void prep_kernel(const float* __restrict__ E) {
    int i = blockIdx.x * blockDim.x + threadIdx.x;
    if (i >= NROWS) return;
    const float4* row = reinterpret_cast<const float4*>(E + (size_t)i * DDIM);
    float s = 0.0f;
#pragma unroll
    for (int q = 0; q < DDIM / 4; q++) {
        float4 v = row[q];
        __nv_bfloat16 b0 = __float2bfloat16(v.x), b1 = __float2bfloat16(v.y);
        __nv_bfloat16 b2 = __float2bfloat16(v.z), b3 = __float2bfloat16(v.w);
        float f0 = __bfloat162float(b0), f1 = __bfloat162float(b1);
        float f2 = __bfloat162float(b2), f3 = __bfloat162float(b3);
        s += f0 * f0 + f1 * f1 + f2 * f2 + f3 * f3;
        g_Ebf[i][4 * q + 0] = b0; g_Ebf[i][4 * q + 1] = b1;
        g_Ebf[i][4 * q + 2] = b2; g_Ebf[i][4 * q + 3] = b3;
    }
    g_sq[i] = s;
}

// 128x128 Gram tile via mma.sync m16n8k16 bf16. 8 warps: 4 (rows) x 2 (cols).
// Each warp: 32 rows x 64 cols. A tile resident; 8 B-tiles streamed.
__global__ void __launch_bounds__(256) gram_mma_kernel() {
    __shared__ __align__(16) char sA[16384];   // 128 rows x 128B, swizzled
    __shared__ __align__(16) char sB[16384];
    __shared__ float s_hj[128];                // -0.5 * sq[j0 + c]

    const int tid  = threadIdx.x;
    const int wid  = tid >> 5;
    const int lane = tid & 31;
    const int i0   = blockIdx.x * 128;
    const int wrow = (wid & 3) * 32;
    const int wcol = (wid >> 2) * 64;
    const int g    = lane >> 2;        // 0..7
    const int q    = lane & 3;         // 0..3

    const uint32_t sAb = smem_u32(sA);
    const uint32_t sBb = smem_u32(sB);

    // Load A tile, swizzled: 16B chunk c of row r stored at chunk (c ^ (r&7)).
#pragma unroll
    for (int l = 0; l < 4; l++) {
        int idx = tid + 256 * l;            // 0..1023
        int r = idx >> 3, c = idx & 7;
        *reinterpret_cast<uint4*>(sA + r * 128 + ((c ^ (r & 7)) << 4)) =
            *reinterpret_cast<const uint4*>(&g_Ebf[i0 + r][c * 8]);
    }

    // Per-lane row offsets: rows i0 + wrow + mt*16 + g (+8)
    float hi[2][2];
#pragma unroll
    for (int mt = 0; mt < 2; mt++) {
        int r0 = i0 + wrow + mt * 16 + g;
        hi[mt][0] = -0.5f * g_sq[r0];
        hi[mt][1] = -0.5f * g_sq[r0 + 8];
    }

    float rs[4] = {0.0f, 0.0f, 0.0f, 0.0f};

    for (int jt = 0; jt < JCHUNK; jt++) {
        const int j0 = (blockIdx.y * JCHUNK + jt) * 128;
        __syncthreads();   // previous iteration's readers done with sB/s_hj
#pragma unroll
        for (int l = 0; l < 4; l++) {
            int idx = tid + 256 * l;
            int r = idx >> 3, c = idx & 7;
            *reinterpret_cast<uint4*>(sB + r * 128 + ((c ^ (r & 7)) << 4)) =
                *reinterpret_cast<const uint4*>(&g_Ebf[j0 + r][c * 8]);
        }
        if (tid < 128) s_hj[tid] = -0.5f * g_sq[j0 + tid];
        __syncthreads();

        float acc[2][8][4];
#pragma unroll
        for (int mt = 0; mt < 2; mt++)
#pragma unroll
            for (int nt = 0; nt < 8; nt++)
#pragma unroll
                for (int e = 0; e < 4; e++) acc[mt][nt][e] = 0.0f;

#pragma unroll
        for (int ks = 0; ks < 4; ks++) {         // K = 64, k16 per step
            const int cb = ks * 2;               // 16B-chunk base of this k-step
            uint32_t a[2][4];
#pragma unroll
            for (int mt = 0; mt < 2; mt++) {
                // lanes 0-15: rows, chunk cb; lanes 16-31: same rows, chunk cb+1
                int r = wrow + mt * 16 + (lane & 15);
                int c = cb + (lane >> 4);
                ldsm_x4(a[mt], sAb + r * 128 + ((c ^ (r & 7)) << 4));
            }
            uint32_t b[4][4];                     // 4 pairs of n-tiles
#pragma unroll
            for (int np = 0; np < 4; np++) {
                // groups of 8 lanes: (rows, cb), (rows, cb+1), (rows+8, cb), (rows+8, cb+1)
                int grp = lane >> 3, r8 = lane & 7;
                int r = wcol + np * 16 + ((grp >> 1) << 3) + r8;
                int c = cb + (grp & 1);
                ldsm_x4(b[np], sBb + r * 128 + ((c ^ (r & 7)) << 4));
            }
#pragma unroll
            for (int mt = 0; mt < 2; mt++)
#pragma unroll
                for (int np = 0; np < 4; np++) {
                    mma_bf16(acc[mt][np * 2 + 0], a[mt], &b[np][0]);
                    mma_bf16(acc[mt][np * 2 + 1], a[mt], &b[np][2]);
                }
        }

        // Fused epilogue: exp(min(0, dot - 0.5 sqi - 0.5 sqj)), row sums
#pragma unroll
        for (int nt = 0; nt < 8; nt++) {
            int lc = wcol + nt * 8 + q * 2;
            float hj0 = s_hj[lc], hj1 = s_hj[lc + 1];
#pragma unroll
            for (int mt = 0; mt < 2; mt++) {
                rs[mt * 2 + 0] += __expf(fminf(acc[mt][nt][0] + hi[mt][0] + hj0, 0.0f))
                                + __expf(fminf(acc[mt][nt][1] + hi[mt][0] + hj1, 0.0f));
                rs[mt * 2 + 1] += __expf(fminf(acc[mt][nt][2] + hi[mt][1] + hj0, 0.0f))
                                + __expf(fminf(acc[mt][nt][3] + hi[mt][1] + hj1, 0.0f));
            }
        }
    }

    // Quad-reduce (lanes 4g..4g+3 hold partials of the same 4 rows)
#pragma unroll
    for (int k = 0; k < 4; k++) {
        rs[k] += __shfl_xor_sync(0xffffffffu, rs[k], 1);
        rs[k] += __shfl_xor_sync(0xffffffffu, rs[k], 2);
    }
    // lane q contributes row (mt = q>>1, half = q&1)
    int row = i0 + wrow + (q >> 1) * 16 + (q & 1) * 8 + g;
    atomicAdd(&g_rowsum[row], rs[q]);
}

__global__ void mse_kernel(const float* __restrict__ yt, const float* __restrict__ yp) {
    int idx = blockIdx.x * blockDim.x + threadIdx.x;
    float4 t = reinterpret_cast<const float4*>(yt)[idx];
    float4 p = reinterpret_cast<const float4*>(yp)[idx];
    float dx = p.x - t.x, dy = p.y - t.y, dz = p.z - t.z, dw = p.w - t.w;
    float s = dx * dx + dy * dy + dz * dz + dw * dw;
#pragma unroll
    for (int o = 16; o > 0; o >>= 1) s += __shfl_down_sync(0xffffffffu, s, o);
    if ((threadIdx.x & 31) == 0) atomicAdd(&g_mse, s);
}

__global__ void final_kernel(float* __restrict__ out) {
    __shared__ float sh[256];
    float s = 0.0f;
    for (int i = threadIdx.x; i < NROWS; i += 256) s += logf(g_rowsum[i]);
    sh[threadIdx.x] = s;
    __syncthreads();
    for (int o = 128; o > 0; o >>= 1) {
        if (threadIdx.x < o) sh[threadIdx.x] += sh[threadIdx.x + o];
        __syncthreads();
    }
    if (threadIdx.x == 0) {
        float kde  = sh[0] / (float)NROWS;
        float IXT  = (logf((float)NROWS) - kde) * 1.44269504088896340736f;
        float dist = g_mse / (float)(NROWS * DDIM);
        out[0] = IXT + 500.0f * dist;
        out[1] = IXT;
        out[2] = dist;
    }
}

extern "C" void kernel_launch(void* const* d_in, const int* in_sizes, int n_in,
                              void* d_out, int out_size) {
    const float* y_true  = (const float*)d_in[0];
    const float* y_pred  = (const float*)d_in[1];
    const float* encoded = (const float*)d_in[2];
    float* out = (float*)d_out;

    init_kernel<<<(NROWS + 255) / 256, 256>>>();
    prep_kernel<<<(NROWS + 255) / 256, 256>>>(encoded);
    mse_kernel<<<(NROWS * DDIM / 4) / 256, 256>>>(y_true, y_pred);
    gram_mma_kernel<<<dim3(NTILE, 8), 256>>>();
    final_kernel<<<1, 256>>>(out);
}

// round 4
// speedup vs baseline: 4.0928x; 1.2938x over previous
#include <cuda_runtime.h>
#include <cuda_bf16.h>
#include <cstdint>
#include <math.h>

#define NROWS 8192
#define DDIM  64
#define NTILE (NROWS / 128)              // 64
#define NPAIRS (NTILE * (NTILE + 1) / 2) // 2080
#define MSE_BLOCKS 512

// ---------------- scratch (__device__ globals; no allocations allowed) ----
__device__ __align__(16) __nv_bfloat16 g_Ebf[NROWS][DDIM];  // 1 MB
__device__ float g_h[NROWS];             // -0.5 * ||x_i||^2 (bf16-derived)
__device__ float g_rowsum[NROWS];
__device__ float g_msep[MSE_BLOCKS];
__device__ unsigned int g_ctr;           // zero-init; self-resetting

__device__ __forceinline__ uint32_t smem_u32(const void* p) {
    uint32_t a;
    asm("{ .reg .u64 t; cvta.to.shared.u64 t, %1; cvt.u32.u64 %0, t; }"
        : "=r"(a) : "l"(p));
    return a;
}
__device__ __forceinline__ void ldsm_x4(uint32_t* r, uint32_t addr) {
    asm volatile("ldmatrix.sync.aligned.m8n8.x4.shared.b16 {%0,%1,%2,%3}, [%4];"
                 : "=r"(r[0]), "=r"(r[1]), "=r"(r[2]), "=r"(r[3]) : "r"(addr));
}
__device__ __forceinline__ void mma_bf16(float* d, const uint32_t* a,
                                         const uint32_t* b) {
    asm volatile(
        "mma.sync.aligned.m16n8k16.row.col.f32.bf16.bf16.f32 "
        "{%0,%1,%2,%3}, {%4,%5,%6,%7}, {%8,%9}, {%0,%1,%2,%3};"
        : "+f"(d[0]), "+f"(d[1]), "+f"(d[2]), "+f"(d[3])
        : "r"(a[0]), "r"(a[1]), "r"(a[2]), "r"(a[3]), "r"(b[0]), "r"(b[1]));
}

// ---------------- kernel 1: quantize + norms + rowsum init + MSE ----------
__global__ void __launch_bounds__(256) prep_fused(const float* __restrict__ E,
                                                  const float* __restrict__ yt,
                                                  const float* __restrict__ yp) {
    const int bid = blockIdx.x, tid = threadIdx.x;
    if (bid < 32) {
        int i = bid * 256 + tid;
        const float4* row = reinterpret_cast<const float4*>(E + (size_t)i * DDIM);
        float s = 0.0f;
#pragma unroll
        for (int qq = 0; qq < DDIM / 4; qq++) {
            float4 v = row[qq];
            __nv_bfloat16 b0 = __float2bfloat16(v.x), b1 = __float2bfloat16(v.y);
            __nv_bfloat16 b2 = __float2bfloat16(v.z), b3 = __float2bfloat16(v.w);
            float f0 = __bfloat162float(b0), f1 = __bfloat162float(b1);
            float f2 = __bfloat162float(b2), f3 = __bfloat162float(b3);
            s += f0 * f0 + f1 * f1 + f2 * f2 + f3 * f3;
            g_Ebf[i][4 * qq + 0] = b0; g_Ebf[i][4 * qq + 1] = b1;
            g_Ebf[i][4 * qq + 2] = b2; g_Ebf[i][4 * qq + 3] = b3;
        }
        g_h[i] = -0.5f * s;
        g_rowsum[i] = 0.0f;
    } else {
        __shared__ float sh[8];
        int idx = (bid - 32) * 256 + tid;     // over 131072 float4s
        float4 t = reinterpret_cast<const float4*>(yt)[idx];
        float4 p = reinterpret_cast<const float4*>(yp)[idx];
        float dx = p.x - t.x, dy = p.y - t.y, dz = p.z - t.z, dw = p.w - t.w;
        float s = dx * dx + dy * dy + dz * dz + dw * dw;
#pragma unroll
        for (int o = 16; o > 0; o >>= 1) s += __shfl_down_sync(0xffffffffu, s, o);
        if ((tid & 31) == 0) sh[tid >> 5] = s;
        __syncthreads();
        if (tid < 8) {
            s = sh[tid];
#pragma unroll
            for (int o = 4; o > 0; o >>= 1) s += __shfl_down_sync(0xffu, s, o);
            if (tid == 0) g_msep[bid - 32] = s;
        }
    }
}

// ---------------- kernel 2: triangular Gram + fused epilogue + final ------
__global__ void __launch_bounds__(256, 2) gram_mma_kernel(float* __restrict__ out) {
    __shared__ __align__(16) char sA[16384];   // 128 rows x 128B, swizzled
    __shared__ __align__(16) char sB[16384];
    __shared__ float s_hj[128];
    __shared__ unsigned int s_last;

    const int tid  = threadIdx.x;
    const int wid  = tid >> 5;
    const int lane = tid & 31;
    const int wrow = (wid & 3) * 32;
    const int wcol = (wid >> 2) * 64;
    const int g    = lane >> 2;        // 0..7
    const int q    = lane & 3;         // 0..3

    // decode upper-triangular pair (ti <= tj)
    int rem = blockIdx.x, ti = 0;
    while (rem >= NTILE - ti) { rem -= NTILE - ti; ti++; }
    const int tj = ti + rem;
    const int i0 = ti * 128, j0 = tj * 128;
    const bool offdiag = (tj > ti);

    const uint32_t sAb = smem_u32(sA);
    const uint32_t sBb = smem_u32(sB);

#pragma unroll
    for (int l = 0; l < 4; l++) {
        int idx = tid + 256 * l;            // 0..1023
        int r = idx >> 3, c = idx & 7;
        *reinterpret_cast<uint4*>(sA + r * 128 + ((c ^ (r & 7)) << 4)) =
            *reinterpret_cast<const uint4*>(&g_Ebf[i0 + r][c * 8]);
        *reinterpret_cast<uint4*>(sB + r * 128 + ((c ^ (r & 7)) << 4)) =
            *reinterpret_cast<const uint4*>(&g_Ebf[j0 + r][c * 8]);
    }
    if (tid < 128) s_hj[tid] = g_h[j0 + tid];
    __syncthreads();

    float hi[2][2];
#pragma unroll
    for (int mt = 0; mt < 2; mt++) {
        int r0 = i0 + wrow + mt * 16 + g;
        hi[mt][0] = g_h[r0];
        hi[mt][1] = g_h[r0 + 8];
    }

    float acc[2][8][4];
#pragma unroll
    for (int mt = 0; mt < 2; mt++)
#pragma unroll
        for (int nt = 0; nt < 8; nt++)
#pragma unroll
            for (int e = 0; e < 4; e++) acc[mt][nt][e] = 0.0f;

#pragma unroll
    for (int ks = 0; ks < 4; ks++) {         // K = 64, k16 per step
        const int cb = ks * 2;
        uint32_t a[2][4];
#pragma unroll
        for (int mt = 0; mt < 2; mt++) {
            int r = wrow + mt * 16 + (lane & 15);
            int c = cb + (lane >> 4);
            ldsm_x4(a[mt], sAb + r * 128 + ((c ^ (r & 7)) << 4));
        }
        uint32_t b[4][4];
#pragma unroll
        for (int np = 0; np < 4; np++) {
            int grp = lane >> 3, r8 = lane & 7;
            int r = wcol + np * 16 + ((grp >> 1) << 3) + r8;
            int c = cb + (grp & 1);
            ldsm_x4(b[np], sBb + r * 128 + ((c ^ (r & 7)) << 4));
        }
#pragma unroll
        for (int mt = 0; mt < 2; mt++)
#pragma unroll
            for (int np = 0; np < 4; np++) {
                mma_bf16(acc[mt][np * 2 + 0], a[mt], &b[np][0]);
                mma_bf16(acc[mt][np * 2 + 1], a[mt], &b[np][2]);
            }
    }

    // epilogue: exp(min(0, dot + hi + hj)); row sums always, col sums if offdiag
    float rs[4] = {0.0f, 0.0f, 0.0f, 0.0f};
#pragma unroll
    for (int nt = 0; nt < 8; nt++) {
        int lc = wcol + nt * 8 + q * 2;
        float hj0 = s_hj[lc], hj1 = s_hj[lc + 1];
        float c0 = 0.0f, c1 = 0.0f;
#pragma unroll
        for (int mt = 0; mt < 2; mt++) {
            float e0 = __expf(fminf(acc[mt][nt][0] + hi[mt][0] + hj0, 0.0f));
            float e1 = __expf(fminf(acc[mt][nt][1] + hi[mt][0] + hj1, 0.0f));
            float e2 = __expf(fminf(acc[mt][nt][2] + hi[mt][1] + hj0, 0.0f));
            float e3 = __expf(fminf(acc[mt][nt][3] + hi[mt][1] + hj1, 0.0f));
            rs[mt * 2 + 0] += e0 + e1;
            rs[mt * 2 + 1] += e2 + e3;
            c0 += e0 + e2;
            c1 += e1 + e3;
        }
        if (offdiag) {
            c0 += __shfl_xor_sync(0xffffffffu, c0, 4);
            c0 += __shfl_xor_sync(0xffffffffu, c0, 8);
            c0 += __shfl_xor_sync(0xffffffffu, c0, 16);
            c1 += __shfl_xor_sync(0xffffffffu, c1, 4);
            c1 += __shfl_xor_sync(0xffffffffu, c1, 8);
            c1 += __shfl_xor_sync(0xffffffffu, c1, 16);
            if (g == nt) {
                atomicAdd(&g_rowsum[j0 + lc], c0);
                atomicAdd(&g_rowsum[j0 + lc + 1], c1);
            }
        }
    }

    // row sums: quad-reduce, one atomic per row per warp
#pragma unroll
    for (int k = 0; k < 4; k++) {
        rs[k] += __shfl_xor_sync(0xffffffffu, rs[k], 1);
        rs[k] += __shfl_xor_sync(0xffffffffu, rs[k], 2);
    }
    int row = i0 + wrow + (q >> 1) * 16 + (q & 1) * 8 + g;
    atomicAdd(&g_rowsum[row], rs[q]);

    // ---- last-CTA final reduction ----
    __threadfence();
    __syncthreads();
    if (tid == 0) {
        unsigned int old = atomicAdd(&g_ctr, 1u);
        s_last = (old == gridDim.x - 1) ? 1u : 0u;
        if (s_last) g_ctr = 0;   // reset for next graph replay
    }
    __syncthreads();
    if (s_last) {
        __shared__ float sh[256];
        float s = 0.0f;
        for (int i = tid; i < NROWS; i += 256) s += logf(__ldcg(&g_rowsum[i]));
        float m = 0.0f;
        for (int i = tid; i < MSE_BLOCKS; i += 256) m += g_msep[i];
        sh[tid] = s;
        __syncthreads();
        for (int o = 128; o > 0; o >>= 1) {
            if (tid < o) sh[tid] += sh[tid + o];
            __syncthreads();
        }
        float stot = sh[0];
        __syncthreads();
        sh[tid] = m;
        __syncthreads();
        for (int o = 128; o > 0; o >>= 1) {
            if (tid < o) sh[tid] += sh[tid + o];
            __syncthreads();
        }
        if (tid == 0) {
            float kde  = stot / (float)NROWS;
            float IXT  = (logf((float)NROWS) - kde) * 1.44269504088896340736f;
            float dist = sh[0] / (float)(NROWS * DDIM);
            out[0] = IXT + 500.0f * dist;
            out[1] = IXT;
            out[2] = dist;
        }
    }
}

extern "C" void kernel_launch(void* const* d_in, const int* in_sizes, int n_in,
                              void* d_out, int out_size) {
    const float* y_true  = (const float*)d_in[0];
    const float* y_pred  = (const float*)d_in[1];
    const float* encoded = (const float*)d_in[2];
    float* out = (float*)d_out;

    prep_fused<<<32 + MSE_BLOCKS, 256>>>(encoded, y_true, y_pred);
    gram_mma_kernel<<<NPAIRS, 256>>>(out);
}

// round 5
// speedup vs baseline: 5.7536x; 1.4058x over previous
#include <cuda_runtime.h>
#include <cuda_bf16.h>
#include <cstdint>
#include <math.h>

#define NROWS 8192
#define DDIM  64
#define NTILE (NROWS / 128)              // 64
#define NPAIRS (NTILE * (NTILE + 1) / 2) // 2080
#define MSE_BLOCKS 512
#define LUT_BLOCKS ((NPAIRS + 255) / 256)
#define THRESH (-20.0f)

// ---------------- scratch (__device__ globals; no allocations allowed) ----
__device__ __align__(16) __nv_bfloat16 g_Ebf[NROWS][DDIM];  // 1 MB
__device__ float g_h[NROWS];             // -0.5 * ||x_i||^2 (bf16-derived)
__device__ float g_rowsum[NROWS];
__device__ float g_msep[MSE_BLOCKS];
__device__ int   g_pair[NPAIRS];         // (ti<<8)|tj
__device__ unsigned int g_ctr;           // zero-init; self-resetting

__device__ __forceinline__ uint32_t smem_u32(const void* p) {
    uint32_t a;
    asm("{ .reg .u64 t; cvta.to.shared.u64 t, %1; cvt.u32.u64 %0, t; }"
        : "=r"(a) : "l"(p));
    return a;
}
__device__ __forceinline__ void ldsm_x4(uint32_t* r, uint32_t addr) {
    asm volatile("ldmatrix.sync.aligned.m8n8.x4.shared.b16 {%0,%1,%2,%3}, [%4];"
                 : "=r"(r[0]), "=r"(r[1]), "=r"(r[2]), "=r"(r[3]) : "r"(addr));
}
__device__ __forceinline__ void mma_bf16(float* d, const uint32_t* a,
                                         const uint32_t* b) {
    asm volatile(
        "mma.sync.aligned.m16n8k16.row.col.f32.bf16.bf16.f32 "
        "{%0,%1,%2,%3}, {%4,%5,%6,%7}, {%8,%9}, {%0,%1,%2,%3};"
        : "+f"(d[0]), "+f"(d[1]), "+f"(d[2]), "+f"(d[3])
        : "r"(a[0]), "r"(a[1]), "r"(a[2]), "r"(a[3]), "r"(b[0]), "r"(b[1]));
}

// ---------------- kernel 1: quantize + norms + MSE + tile LUT -------------
__global__ void __launch_bounds__(256) prep_fused(const float* __restrict__ E,
                                                  const float* __restrict__ yt,
                                                  const float* __restrict__ yp) {
    const int bid = blockIdx.x, tid = threadIdx.x;
    if (bid < 32) {
        int i = bid * 256 + tid;
        const float4* row = reinterpret_cast<const float4*>(E + (size_t)i * DDIM);
        float s = 0.0f;
#pragma unroll
        for (int qq = 0; qq < DDIM / 4; qq++) {
            float4 v = row[qq];
            __nv_bfloat16 b0 = __float2bfloat16(v.x), b1 = __float2bfloat16(v.y);
            __nv_bfloat16 b2 = __float2bfloat16(v.z), b3 = __float2bfloat16(v.w);
            float f0 = __bfloat162float(b0), f1 = __bfloat162float(b1);
            float f2 = __bfloat162float(b2), f3 = __bfloat162float(b3);
            s += f0 * f0 + f1 * f1 + f2 * f2 + f3 * f3;
            g_Ebf[i][4 * qq + 0] = b0; g_Ebf[i][4 * qq + 1] = b1;
            g_Ebf[i][4 * qq + 2] = b2; g_Ebf[i][4 * qq + 3] = b3;
        }
        g_h[i] = -0.5f * s;
        g_rowsum[i] = 0.0f;
    } else if (bid < 32 + MSE_BLOCKS) {
        __shared__ float sh[8];
        int idx = (bid - 32) * 256 + tid;     // over 131072 float4s
        float4 t = reinterpret_cast<const float4*>(yt)[idx];
        float4 p = reinterpret_cast<const float4*>(yp)[idx];
        float dx = p.x - t.x, dy = p.y - t.y, dz = p.z - t.z, dw = p.w - t.w;
        float s = dx * dx + dy * dy + dz * dz + dw * dw;
#pragma unroll
        for (int o = 16; o > 0; o >>= 1) s += __shfl_down_sync(0xffffffffu, s, o);
        if ((tid & 31) == 0) sh[tid >> 5] = s;
        __syncthreads();
        if (tid < 8) {
            s = sh[tid];
#pragma unroll
            for (int o = 4; o > 0; o >>= 1) s += __shfl_down_sync(0xffu, s, o);
            if (tid == 0) g_msep[bid - 32] = s;
        }
    } else {
        int p = (bid - 32 - MSE_BLOCKS) * 256 + tid;
        if (p < NPAIRS) {
            float bf = 2.0f * NTILE + 1.0f;
            int ti = (int)((bf - sqrtf(bf * bf - 8.0f * (float)p)) * 0.5f);
            if (ti < 0) ti = 0;
            if (ti > NTILE - 1) ti = NTILE - 1;
            int start = ti * NTILE - (ti * (ti - 1)) / 2;
            while (start > p) { ti--; start = ti * NTILE - (ti * (ti - 1)) / 2; }
            while (p - start >= NTILE - ti) { start += NTILE - ti; ti++; }
            g_pair[p] = (ti << 8) | (ti + (p - start));
        }
    }
}

// ---------------- kernel 2: triangular Gram + pruned epilogue + final -----
__global__ void __launch_bounds__(256, 2) gram_mma_kernel(float* __restrict__ out) {
    __shared__ __align__(16) char sA[16384];   // 128 rows x 128B, swizzled
    __shared__ __align__(16) char sB[16384];
    __shared__ float s_hj[128];
    __shared__ unsigned int s_last;

    const int tid  = threadIdx.x;
    const int wid  = tid >> 5;
    const int lane = tid & 31;
    const int wrow = (wid & 3) * 32;
    const int wcol = (wid >> 2) * 64;
    const int g    = lane >> 2;        // 0..7
    const int q    = lane & 3;         // 0..3

    const int pr = g_pair[blockIdx.x];
    const int ti = pr >> 8, tj = pr & 255;
    const int i0 = ti * 128, j0 = tj * 128;
    const bool offdiag = (tj > ti);

    const uint32_t sAb = smem_u32(sA);
    const uint32_t sBb = smem_u32(sB);

#pragma unroll
    for (int l = 0; l < 4; l++) {
        int idx = tid + 256 * l;            // 0..1023
        int r = idx >> 3, c = idx & 7;
        *reinterpret_cast<uint4*>(sA + r * 128 + ((c ^ (r & 7)) << 4)) =
            *reinterpret_cast<const uint4*>(&g_Ebf[i0 + r][c * 8]);
        *reinterpret_cast<uint4*>(sB + r * 128 + ((c ^ (r & 7)) << 4)) =
            *reinterpret_cast<const uint4*>(&g_Ebf[j0 + r][c * 8]);
    }
    if (tid < 128) s_hj[tid] = g_h[j0 + tid];
    __syncthreads();

    float hi[2][2];
#pragma unroll
    for (int mt = 0; mt < 2; mt++) {
        int r0 = i0 + wrow + mt * 16 + g;
        hi[mt][0] = g_h[r0];
        hi[mt][1] = g_h[r0 + 8];
    }

    float acc[2][8][4];
#pragma unroll
    for (int mt = 0; mt < 2; mt++)
#pragma unroll
        for (int nt = 0; nt < 8; nt++)
#pragma unroll
            for (int e = 0; e < 4; e++) acc[mt][nt][e] = 0.0f;

#pragma unroll
    for (int ks = 0; ks < 4; ks++) {         // K = 64, k16 per step
        const int cb = ks * 2;
        uint32_t a[2][4];
#pragma unroll
        for (int mt = 0; mt < 2; mt++) {
            int r = wrow + mt * 16 + (lane & 15);
            int c = cb + (lane >> 4);
            ldsm_x4(a[mt], sAb + r * 128 + ((c ^ (r & 7)) << 4));
        }
        uint32_t b[4][4];
#pragma unroll
        for (int np = 0; np < 4; np++) {
            int grp = lane >> 3, r8 = lane & 7;
            int r = wcol + np * 16 + ((grp >> 1) << 3) + r8;
            int c = cb + (grp & 1);
            ldsm_x4(b[np], sBb + r * 128 + ((c ^ (r & 7)) << 4));
        }
#pragma unroll
        for (int mt = 0; mt < 2; mt++)
#pragma unroll
            for (int np = 0; np < 4; np++) {
                mma_bf16(acc[mt][np * 2 + 0], a[mt], &b[np][0]);
                mma_bf16(acc[mt][np * 2 + 1], a[mt], &b[np][2]);
            }
    }

    // ---- pruning pass: exact args, warp-max, no MUFU --------------------
    float wmax = -1e30f;
#pragma unroll
    for (int nt = 0; nt < 8; nt++) {
        int lc = wcol + nt * 8 + q * 2;
        float hj0 = s_hj[lc], hj1 = s_hj[lc + 1];
#pragma unroll
        for (int mt = 0; mt < 2; mt++) {
            float m0 = fmaxf(acc[mt][nt][0] + (hi[mt][0] + hj0),
                             acc[mt][nt][1] + (hi[mt][0] + hj1));
            float m1 = fmaxf(acc[mt][nt][2] + (hi[mt][1] + hj0),
                             acc[mt][nt][3] + (hi[mt][1] + hj1));
            wmax = fmaxf(wmax, fmaxf(m0, m1));
        }
    }

    if (__any_sync(0xffffffffu, wmax > THRESH)) {
        // heavy path: exp + row sums (+ col sums if offdiag)
        float rs[4] = {0.0f, 0.0f, 0.0f, 0.0f};
#pragma unroll
        for (int nt = 0; nt < 8; nt++) {
            int lc = wcol + nt * 8 + q * 2;
            float hj0 = s_hj[lc], hj1 = s_hj[lc + 1];
            float c0 = 0.0f, c1 = 0.0f;
#pragma unroll
            for (int mt = 0; mt < 2; mt++) {
                float e0 = __expf(fminf(acc[mt][nt][0] + hi[mt][0] + hj0, 0.0f));
                float e1 = __expf(fminf(acc[mt][nt][1] + hi[mt][0] + hj1, 0.0f));
                float e2 = __expf(fminf(acc[mt][nt][2] + hi[mt][1] + hj0, 0.0f));
                float e3 = __expf(fminf(acc[mt][nt][3] + hi[mt][1] + hj1, 0.0f));
                rs[mt * 2 + 0] += e0 + e1;
                rs[mt * 2 + 1] += e2 + e3;
                c0 += e0 + e2;
                c1 += e1 + e3;
            }
            if (offdiag) {
                c0 += __shfl_xor_sync(0xffffffffu, c0, 4);
                c0 += __shfl_xor_sync(0xffffffffu, c0, 8);
                c0 += __shfl_xor_sync(0xffffffffu, c0, 16);
                c1 += __shfl_xor_sync(0xffffffffu, c1, 4);
                c1 += __shfl_xor_sync(0xffffffffu, c1, 8);
                c1 += __shfl_xor_sync(0xffffffffu, c1, 16);
                if (g == nt) {
                    atomicAdd(&g_rowsum[j0 + lc], c0);
                    atomicAdd(&g_rowsum[j0 + lc + 1], c1);
                }
            }
        }
#pragma unroll
        for (int k = 0; k < 4; k++) {
            rs[k] += __shfl_xor_sync(0xffffffffu, rs[k], 1);
            rs[k] += __shfl_xor_sync(0xffffffffu, rs[k], 2);
        }
        int row = i0 + wrow + (q >> 1) * 16 + (q & 1) * 8 + g;
        atomicAdd(&g_rowsum[row], rs[q]);
    }

    // ---- last-CTA final reduction ----
    __threadfence();
    __syncthreads();
    if (tid == 0) {
        unsigned int old = atomicAdd(&g_ctr, 1u);
        s_last = (old == gridDim.x - 1) ? 1u : 0u;
        if (s_last) g_ctr = 0;   // reset for next graph replay
    }
    __syncthreads();
    if (s_last) {
        __shared__ float sh[256];
        float s = 0.0f;
        for (int i = tid; i < NROWS; i += 256) s += logf(__ldcg(&g_rowsum[i]));
        float m = 0.0f;
        for (int i = tid; i < MSE_BLOCKS; i += 256) m += g_msep[i];
        sh[tid] = s;
        __syncthreads();
        for (int o = 128; o > 0; o >>= 1) {
            if (tid < o) sh[tid] += sh[tid + o];
            __syncthreads();
        }
        float stot = sh[0];
        __syncthreads();
        sh[tid] = m;
        __syncthreads();
        for (int o = 128; o > 0; o >>= 1) {
            if (tid < o) sh[tid] += sh[tid + o];
            __syncthreads();
        }
        if (tid == 0) {
            float kde  = stot / (float)NROWS;
            float IXT  = (logf((float)NROWS) - kde) * 1.44269504088896340736f;
            float dist = sh[0] / (float)(NROWS * DDIM);
            out[0] = IXT + 500.0f * dist;
            out[1] = IXT;
            out[2] = dist;
        }
    }
}

extern "C" void kernel_launch(void* const* d_in, const int* in_sizes, int n_in,
                              void* d_out, int out_size) {
    const float* y_true  = (const float*)d_in[0];
    const float* y_pred  = (const float*)d_in[1];
    const float* encoded = (const float*)d_in[2];
    float* out = (float*)d_out;

    prep_fused<<<32 + MSE_BLOCKS + LUT_BLOCKS, 256>>>(encoded, y_true, y_pred);
    gram_mma_kernel<<<NPAIRS, 256>>>(out);
}

// round 6
// speedup vs baseline: 6.0669x; 1.0544x over previous
#include <cuda_runtime.h>
#include <cuda_bf16.h>
#include <cstdint>
#include <math.h>

#define NROWS 8192
#define DDIM  64
#define NTILE (NROWS / 128)              // 64
#define NPAIRS (NTILE * (NTILE + 1) / 2) // 2080
#define MSE_BLOCKS 512
#define LUT_BLOCKS ((NPAIRS + 255) / 256)
#define THRESH (-20.0f)
#define GRID 304
#define CHUNK ((NPAIRS + GRID - 1) / GRID)   // 7

// dynamic smem layout (double-buffered)
#define SM_A(b)  ((b) * 16384)
#define SM_B(b)  (32768 + (b) * 16384)
#define SM_HI(b) (65536 + (b) * 512)
#define SM_HJ(b) (66560 + (b) * 512)
#define SM_DYN   67584

// ---------------- scratch (__device__ globals; no allocations allowed) ----
__device__ __align__(16) __nv_bfloat16 g_Ebf[NROWS][DDIM];  // 1 MB
__device__ float g_h[NROWS];             // -0.5 * ||x_i||^2 (bf16-derived)
__device__ float g_rowsum[NROWS];
__device__ float g_msep[MSE_BLOCKS];
__device__ int   g_pair[NPAIRS];         // (ti<<8)|tj
__device__ unsigned int g_ctr;           // zero-init; self-resetting

__device__ __forceinline__ uint32_t smem_u32(const void* p) {
    uint32_t a;
    asm("{ .reg .u64 t; cvta.to.shared.u64 t, %1; cvt.u32.u64 %0, t; }"
        : "=r"(a) : "l"(p));
    return a;
}
__device__ __forceinline__ void ldsm_x4(uint32_t* r, uint32_t addr) {
    asm volatile("ldmatrix.sync.aligned.m8n8.x4.shared.b16 {%0,%1,%2,%3}, [%4];"
                 : "=r"(r[0]), "=r"(r[1]), "=r"(r[2]), "=r"(r[3]) : "r"(addr));
}
__device__ __forceinline__ void mma_bf16(float* d, const uint32_t* a,
                                         const uint32_t* b) {
    asm volatile(
        "mma.sync.aligned.m16n8k16.row.col.f32.bf16.bf16.f32 "
        "{%0,%1,%2,%3}, {%4,%5,%6,%7}, {%8,%9}, {%0,%1,%2,%3};"
        : "+f"(d[0]), "+f"(d[1]), "+f"(d[2]), "+f"(d[3])
        : "r"(a[0]), "r"(a[1]), "r"(a[2]), "r"(a[3]), "r"(b[0]), "r"(b[1]));
}
__device__ __forceinline__ void cp16(uint32_t dst, const void* src) {
    asm volatile("cp.async.cg.shared.global [%0], [%1], 16;"
                 :: "r"(dst), "l"(src) : "memory");
}
#define CP_COMMIT() asm volatile("cp.async.commit_group;" ::: "memory")
#define CP_WAIT(n)  asm volatile("cp.async.wait_group %0;" :: "n"(n) : "memory")

// ---------------- kernel 1: quantize + norms + MSE + tile LUT -------------
__global__ void __launch_bounds__(256) prep_fused(const float* __restrict__ E,
                                                  const float* __restrict__ yt,
                                                  const float* __restrict__ yp) {
    const int bid = blockIdx.x, tid = threadIdx.x;
    if (bid < 32) {
        int i = bid * 256 + tid;
        const float4* row = reinterpret_cast<const float4*>(E + (size_t)i * DDIM);
        float s = 0.0f;
#pragma unroll
        for (int qq = 0; qq < DDIM / 4; qq++) {
            float4 v = row[qq];
            __nv_bfloat16 b0 = __float2bfloat16(v.x), b1 = __float2bfloat16(v.y);
            __nv_bfloat16 b2 = __float2bfloat16(v.z), b3 = __float2bfloat16(v.w);
            float f0 = __bfloat162float(b0), f1 = __bfloat162float(b1);
            float f2 = __bfloat162float(b2), f3 = __bfloat162float(b3);
            s += f0 * f0 + f1 * f1 + f2 * f2 + f3 * f3;
            g_Ebf[i][4 * qq + 0] = b0; g_Ebf[i][4 * qq + 1] = b1;
            g_Ebf[i][4 * qq + 2] = b2; g_Ebf[i][4 * qq + 3] = b3;
        }
        g_h[i] = -0.5f * s;
        g_rowsum[i] = 0.0f;
    } else if (bid < 32 + MSE_BLOCKS) {
        __shared__ float sh[8];
        int idx = (bid - 32) * 256 + tid;     // over 131072 float4s
        float4 t = reinterpret_cast<const float4*>(yt)[idx];
        float4 p = reinterpret_cast<const float4*>(yp)[idx];
        float dx = p.x - t.x, dy = p.y - t.y, dz = p.z - t.z, dw = p.w - t.w;
        float s = dx * dx + dy * dy + dz * dz + dw * dw;
#pragma unroll
        for (int o = 16; o > 0; o >>= 1) s += __shfl_down_sync(0xffffffffu, s, o);
        if ((tid & 31) == 0) sh[tid >> 5] = s;
        __syncthreads();
        if (tid < 8) {
            s = sh[tid];
#pragma unroll
            for (int o = 4; o > 0; o >>= 1) s += __shfl_down_sync(0xffu, s, o);
            if (tid == 0) g_msep[bid - 32] = s;
        }
    } else {
        int p = (bid - 32 - MSE_BLOCKS) * 256 + tid;
        if (p < NPAIRS) {
            float bf = 2.0f * NTILE + 1.0f;
            int ti = (int)((bf - sqrtf(bf * bf - 8.0f * (float)p)) * 0.5f);
            if (ti < 0) ti = 0;
            if (ti > NTILE - 1) ti = NTILE - 1;
            int start = ti * NTILE - (ti * (ti - 1)) / 2;
            while (start > p) { ti--; start = ti * NTILE - (ti * (ti - 1)) / 2; }
            while (p - start >= NTILE - ti) { start += NTILE - ti; ti++; }
            g_pair[p] = (ti << 8) | (ti + (p - start));
        }
    }
}

// ---------------- kernel 2: persistent triangular Gram, double-buffered ---
__global__ void __launch_bounds__(256, 2) gram_mma_kernel(float* __restrict__ out) {
    extern __shared__ __align__(16) char dyn[];
    __shared__ unsigned int s_last;
    __shared__ float sh_red[256];

    const int tid  = threadIdx.x;
    const int wid  = tid >> 5;
    const int lane = tid & 31;
    const int wrow = (wid & 3) * 32;
    const int wcol = (wid >> 2) * 64;
    const int g    = lane >> 2;        // 0..7
    const int q    = lane & 3;         // 0..3
    const uint32_t db = smem_u32(dyn);

    const int t_beg = blockIdx.x * CHUNK;
    const int t_end = min(t_beg + CHUNK, NPAIRS);

    // per-thread load slots: 4 chunks of A + 4 of B (row r, 16B chunk c)
    int lr[4], lcx[4];
#pragma unroll
    for (int l = 0; l < 4; l++) {
        int idx = tid + 256 * l;
        lr[l] = idx >> 3;
        lcx[l] = idx & 7;
    }

    if (t_beg < t_end) {
        int pr_cur = __ldg(&g_pair[t_beg]);
        // preamble prefetch into buffer 0
        {
            int i0 = (pr_cur >> 8) * 128, j0 = (pr_cur & 255) * 128;
#pragma unroll
            for (int l = 0; l < 4; l++) {
                int r = lr[l], c = lcx[l];
                uint32_t sw = (uint32_t)(r * 128 + ((c ^ (r & 7)) << 4));
                cp16(db + SM_A(0) + sw, &g_Ebf[i0 + r][c * 8]);
                cp16(db + SM_B(0) + sw, &g_Ebf[j0 + r][c * 8]);
            }
            if (tid < 32)            cp16(db + SM_HI(0) + tid * 16, &g_h[i0 + tid * 4]);
            else if (tid < 64)       cp16(db + SM_HJ(0) + (tid - 32) * 16, &g_h[j0 + (tid - 32) * 4]);
            CP_COMMIT();
        }

        int cur = 0;
        for (int t = t_beg; t < t_end; t++) {
            int pr_nxt = 0;
            if (t + 1 < t_end) {
                pr_nxt = __ldg(&g_pair[t + 1]);
                int i0 = (pr_nxt >> 8) * 128, j0 = (pr_nxt & 255) * 128;
                int nb = cur ^ 1;
#pragma unroll
                for (int l = 0; l < 4; l++) {
                    int r = lr[l], c = lcx[l];
                    uint32_t sw = (uint32_t)(r * 128 + ((c ^ (r & 7)) << 4));
                    cp16(db + SM_A(nb) + sw, &g_Ebf[i0 + r][c * 8]);
                    cp16(db + SM_B(nb) + sw, &g_Ebf[j0 + r][c * 8]);
                }
                if (tid < 32)      cp16(db + SM_HI(nb) + tid * 16, &g_h[i0 + tid * 4]);
                else if (tid < 64) cp16(db + SM_HJ(nb) + (tid - 32) * 16, &g_h[j0 + (tid - 32) * 4]);
                CP_COMMIT();
                CP_WAIT(1);          // current buffer's group done
            } else {
                CP_WAIT(0);
            }
            __syncthreads();

            const int ti = pr_cur >> 8, tj = pr_cur & 255;
            const int i0 = ti * 128, j0 = tj * 128;
            const bool offdiag = (tj > ti);
            const uint32_t sAb = db + SM_A(cur);
            const uint32_t sBb = db + SM_B(cur);
            const float* s_hi = reinterpret_cast<const float*>(dyn + SM_HI(cur));
            const float* s_hj = reinterpret_cast<const float*>(dyn + SM_HJ(cur));

            float hi[2][2];
#pragma unroll
            for (int mt = 0; mt < 2; mt++) {
                int r0 = wrow + mt * 16 + g;
                hi[mt][0] = s_hi[r0];
                hi[mt][1] = s_hi[r0 + 8];
            }

            float acc[2][8][4];
#pragma unroll
            for (int mt = 0; mt < 2; mt++)
#pragma unroll
                for (int nt = 0; nt < 8; nt++)
#pragma unroll
                    for (int e = 0; e < 4; e++) acc[mt][nt][e] = 0.0f;

#pragma unroll
            for (int ks = 0; ks < 4; ks++) {       // K = 64
                const int cb = ks * 2;
                uint32_t a[2][4];
#pragma unroll
                for (int mt = 0; mt < 2; mt++) {
                    int r = wrow + mt * 16 + (lane & 15);
                    int c = cb + (lane >> 4);
                    ldsm_x4(a[mt], sAb + r * 128 + ((c ^ (r & 7)) << 4));
                }
                uint32_t b[4][4];
#pragma unroll
                for (int np = 0; np < 4; np++) {
                    int grp = lane >> 3, r8 = lane & 7;
                    int r = wcol + np * 16 + ((grp >> 1) << 3) + r8;
                    int c = cb + (grp & 1);
                    ldsm_x4(b[np], sBb + r * 128 + ((c ^ (r & 7)) << 4));
                }
#pragma unroll
                for (int mt = 0; mt < 2; mt++)
#pragma unroll
                    for (int np = 0; np < 4; np++) {
                        mma_bf16(acc[mt][np * 2 + 0], a[mt], &b[np][0]);
                        mma_bf16(acc[mt][np * 2 + 1], a[mt], &b[np][2]);
                    }
            }

            // pruning pass: exact args, warp max, no MUFU
            float wmax = -1e30f;
#pragma unroll
            for (int nt = 0; nt < 8; nt++) {
                int lc = wcol + nt * 8 + q * 2;
                float hj0 = s_hj[lc], hj1 = s_hj[lc + 1];
#pragma unroll
                for (int mt = 0; mt < 2; mt++) {
                    float m0 = fmaxf(acc[mt][nt][0] + (hi[mt][0] + hj0),
                                     acc[mt][nt][1] + (hi[mt][0] + hj1));
                    float m1 = fmaxf(acc[mt][nt][2] + (hi[mt][1] + hj0),
                                     acc[mt][nt][3] + (hi[mt][1] + hj1));
                    wmax = fmaxf(wmax, fmaxf(m0, m1));
                }
            }

            if (__any_sync(0xffffffffu, wmax > THRESH)) {
                float rs[4] = {0.0f, 0.0f, 0.0f, 0.0f};
#pragma unroll
                for (int nt = 0; nt < 8; nt++) {
                    int lc = wcol + nt * 8 + q * 2;
                    float hj0 = s_hj[lc], hj1 = s_hj[lc + 1];
                    float c0 = 0.0f, c1 = 0.0f;
#pragma unroll
                    for (int mt = 0; mt < 2; mt++) {
                        float e0 = __expf(fminf(acc[mt][nt][0] + hi[mt][0] + hj0, 0.0f));
                        float e1 = __expf(fminf(acc[mt][nt][1] + hi[mt][0] + hj1, 0.0f));
                        float e2 = __expf(fminf(acc[mt][nt][2] + hi[mt][1] + hj0, 0.0f));
                        float e3 = __expf(fminf(acc[mt][nt][3] + hi[mt][1] + hj1, 0.0f));
                        rs[mt * 2 + 0] += e0 + e1;
                        rs[mt * 2 + 1] += e2 + e3;
                        c0 += e0 + e2;
                        c1 += e1 + e3;
                    }
                    if (offdiag) {
                        c0 += __shfl_xor_sync(0xffffffffu, c0, 4);
                        c0 += __shfl_xor_sync(0xffffffffu, c0, 8);
                        c0 += __shfl_xor_sync(0xffffffffu, c0, 16);
                        c1 += __shfl_xor_sync(0xffffffffu, c1, 4);
                        c1 += __shfl_xor_sync(0xffffffffu, c1, 8);
                        c1 += __shfl_xor_sync(0xffffffffu, c1, 16);
                        if (g == nt) {
                            atomicAdd(&g_rowsum[j0 + lc], c0);
                            atomicAdd(&g_rowsum[j0 + lc + 1], c1);
                        }
                    }
                }
#pragma unroll
                for (int k = 0; k < 4; k++) {
                    rs[k] += __shfl_xor_sync(0xffffffffu, rs[k], 1);
                    rs[k] += __shfl_xor_sync(0xffffffffu, rs[k], 2);
                }
                int row = i0 + wrow + (q >> 1) * 16 + (q & 1) * 8 + g;
                atomicAdd(&g_rowsum[row], rs[q]);
            }

            __syncthreads();   // all reads of buf[cur] done before it is refilled
            pr_cur = pr_nxt;
            cur ^= 1;
        }
    }

    // ---- last-CTA final reduction ----
    __threadfence();
    __syncthreads();
    if (tid == 0) {
        unsigned int old = atomicAdd(&g_ctr, 1u);
        s_last = (old == gridDim.x - 1) ? 1u : 0u;
        if (s_last) g_ctr = 0;   // reset for next graph replay
    }
    __syncthreads();
    if (s_last) {
        float s = 0.0f;
        for (int i = tid; i < NROWS; i += 256) s += logf(__ldcg(&g_rowsum[i]));
        float m = 0.0f;
        for (int i = tid; i < MSE_BLOCKS; i += 256) m += g_msep[i];
        sh_red[tid] = s;
        __syncthreads();
        for (int o = 128; o > 0; o >>= 1) {
            if (tid < o) sh_red[tid] += sh_red[tid + o];
            __syncthreads();
        }
        float stot = sh_red[0];
        __syncthreads();
        sh_red[tid] = m;
        __syncthreads();
        for (int o = 128; o > 0; o >>= 1) {
            if (tid < o) sh_red[tid] += sh_red[tid + o];
            __syncthreads();
        }
        if (tid == 0) {
            float kde  = stot / (float)NROWS;
            float IXT  = (logf((float)NROWS) - kde) * 1.44269504088896340736f;
            float dist = sh_red[0] / (float)(NROWS * DDIM);
            out[0] = IXT + 500.0f * dist;
            out[1] = IXT;
            out[2] = dist;
        }
    }
}

extern "C" void kernel_launch(void* const* d_in, const int* in_sizes, int n_in,
                              void* d_out, int out_size) {
    const float* y_true  = (const float*)d_in[0];
    const float* y_pred  = (const float*)d_in[1];
    const float* encoded = (const float*)d_in[2];
    float* out = (float*)d_out;

    static bool attr_done = false;
    if (!attr_done) {
        cudaFuncSetAttribute(gram_mma_kernel,
                             cudaFuncAttributeMaxDynamicSharedMemorySize, SM_DYN);
        attr_done = true;
    }

    prep_fused<<<32 + MSE_BLOCKS + LUT_BLOCKS, 256>>>(encoded, y_true, y_pred);
    gram_mma_kernel<<<GRID, 256, SM_DYN>>>(out);
}

// round 7
// speedup vs baseline: 6.1077x; 1.0067x over previous
#include <cuda_runtime.h>
#include <cuda_bf16.h>
#include <cuda_fp8.h>
#include <cstdint>
#include <math.h>

#define NROWS 8192
#define DDIM  64
#define NTILE 64
#define NPAIRS 2080
#define MSE_BLOCKS 512
#define LUT_BLOCKS ((NPAIRS + 255) / 256)
#define THRESH (-20.0f)
#define GRID 304
#define CHUNK ((NPAIRS + GRID - 1) / GRID)   // 7

// 3-stage dynamic smem: per stage A(8K) + B(8K) + hi(512) + hj(512)
#define STAGE_BYTES 17408
#define SM_A_OFF    0
#define SM_B_OFF    8192
#define SM_HI_OFF   16384
#define SM_HJ_OFF   16896
#define SM_DYN      (3 * STAGE_BYTES)        // 52224

// ---------------- scratch (__device__ globals; no allocations allowed) ----
__device__ __align__(16) uint8_t g_E8[NROWS][DDIM];   // fp8 e4m3, 512 KB
__device__ float g_h[NROWS];             // -0.5 * ||x_i||^2 (fp8-derived)
__device__ float g_rowsum[NROWS];
__device__ float g_msep[MSE_BLOCKS];
__device__ int   g_pair[NPAIRS];         // (ti<<8)|tj
__device__ unsigned int g_ctr;           // zero-init; self-resetting

__device__ __forceinline__ uint32_t smem_u32(const void* p) {
    uint32_t a;
    asm("{ .reg .u64 t; cvta.to.shared.u64 t, %1; cvt.u32.u64 %0, t; }"
        : "=r"(a) : "l"(p));
    return a;
}
__device__ __forceinline__ void ldsm_x4(uint32_t* r, uint32_t addr) {
    asm volatile("ldmatrix.sync.aligned.m8n8.x4.shared.b16 {%0,%1,%2,%3}, [%4];"
                 : "=r"(r[0]), "=r"(r[1]), "=r"(r[2]), "=r"(r[3]) : "r"(addr));
}
// fp8 e4m3 MMA, accumulate
__device__ __forceinline__ void mma_fp8(float* d, const uint32_t* a,
                                        const uint32_t* b) {
    asm volatile(
        "mma.sync.aligned.m16n8k32.row.col.f32.e4m3.e4m3.f32 "
        "{%0,%1,%2,%3}, {%4,%5,%6,%7}, {%8,%9}, {%0,%1,%2,%3};"
        : "+f"(d[0]), "+f"(d[1]), "+f"(d[2]), "+f"(d[3])
        : "r"(a[0]), "r"(a[1]), "r"(a[2]), "r"(a[3]), "r"(b[0]), "r"(b[1]));
}
// fp8 e4m3 MMA, C = 0 (defines d, no init needed)
__device__ __forceinline__ void mma_fp8_zc(float* d, const uint32_t* a,
                                           const uint32_t* b) {
    asm volatile(
        "mma.sync.aligned.m16n8k32.row.col.f32.e4m3.e4m3.f32 "
        "{%0,%1,%2,%3}, {%4,%5,%6,%7}, {%8,%9}, {%10,%11,%12,%13};"
        : "=f"(d[0]), "=f"(d[1]), "=f"(d[2]), "=f"(d[3])
        : "r"(a[0]), "r"(a[1]), "r"(a[2]), "r"(a[3]), "r"(b[0]), "r"(b[1]),
          "f"(0.0f), "f"(0.0f), "f"(0.0f), "f"(0.0f));
}
__device__ __forceinline__ void cp16(uint32_t dst, const void* src) {
    asm volatile("cp.async.cg.shared.global [%0], [%1], 16;"
                 :: "r"(dst), "l"(src) : "memory");
}
#define CP_COMMIT() asm volatile("cp.async.commit_group;" ::: "memory")
#define CP_WAIT(n)  asm volatile("cp.async.wait_group %0;" :: "n"(n) : "memory")

// tile row r (0..127), 16B chunk c (0..3) -> swizzled byte offset in 8KB tile
// two tile rows per 128B line; conflict-free for ldmatrix (verified XOR sets)
__device__ __forceinline__ uint32_t tile_addr(int r, int c) {
    return (uint32_t)(((r >> 1) << 7) +
                      (((((r & 1) << 2) | c) ^ ((r >> 1) & 7)) << 4));
}

// ---------------- kernel 1: quantize + norms + MSE + tile LUT -------------
__global__ void __launch_bounds__(256) prep_fused(const float* __restrict__ E,
                                                  const float* __restrict__ yt,
                                                  const float* __restrict__ yp) {
    const int bid = blockIdx.x, tid = threadIdx.x;
    if (bid < 32) {
        int i = bid * 256 + tid;
        const float4* row = reinterpret_cast<const float4*>(E + (size_t)i * DDIM);
        uint32_t packed[16];
        float s = 0.0f;
#pragma unroll
        for (int qq = 0; qq < 16; qq++) {
            float4 v = row[qq];
            __nv_fp8_e4m3 a0(v.x), a1(v.y), a2(v.z), a3(v.w);
            float f0 = float(a0), f1 = float(a1), f2 = float(a2), f3 = float(a3);
            s += f0 * f0 + f1 * f1 + f2 * f2 + f3 * f3;
            packed[qq] = (uint32_t)a0.__x | ((uint32_t)a1.__x << 8) |
                         ((uint32_t)a2.__x << 16) | ((uint32_t)a3.__x << 24);
        }
        uint4* dst = reinterpret_cast<uint4*>(g_E8[i]);
#pragma unroll
        for (int w = 0; w < 4; w++)
            dst[w] = make_uint4(packed[4 * w], packed[4 * w + 1],
                                packed[4 * w + 2], packed[4 * w + 3]);
        g_h[i] = -0.5f * s;
        g_rowsum[i] = 0.0f;
    } else if (bid < 32 + MSE_BLOCKS) {
        __shared__ float sh[8];
        int idx = (bid - 32) * 256 + tid;     // over 131072 float4s
        float4 t = reinterpret_cast<const float4*>(yt)[idx];
        float4 p = reinterpret_cast<const float4*>(yp)[idx];
        float dx = p.x - t.x, dy = p.y - t.y, dz = p.z - t.z, dw = p.w - t.w;
        float s = dx * dx + dy * dy + dz * dz + dw * dw;
#pragma unroll
        for (int o = 16; o > 0; o >>= 1) s += __shfl_down_sync(0xffffffffu, s, o);
        if ((tid & 31) == 0) sh[tid >> 5] = s;
        __syncthreads();
        if (tid < 8) {
            s = sh[tid];
#pragma unroll
            for (int o = 4; o > 0; o >>= 1) s += __shfl_down_sync(0xffu, s, o);
            if (tid == 0) g_msep[bid - 32] = s;
        }
    } else {
        int p = (bid - 32 - MSE_BLOCKS) * 256 + tid;
        if (p < NPAIRS) {
            float bf = 2.0f * NTILE + 1.0f;
            int ti = (int)((bf - sqrtf(bf * bf - 8.0f * (float)p)) * 0.5f);
            if (ti < 0) ti = 0;
            if (ti > NTILE - 1) ti = NTILE - 1;
            int start = ti * NTILE - (ti * (ti - 1)) / 2;
            while (start > p) { ti--; start = ti * NTILE - (ti * (ti - 1)) / 2; }
            while (p - start >= NTILE - ti) { start += NTILE - ti; ti++; }
            g_pair[p] = (ti << 8) | (ti + (p - start));
        }
    }
}

__device__ __forceinline__ void prefetch_tile(uint32_t sbase, int pr, int tid) {
    const int i0 = (pr >> 8) * 128, j0 = (pr & 255) * 128;
#pragma unroll
    for (int l = 0; l < 2; l++) {
        int idx = tid + 256 * l;          // 0..511
        int r = idx >> 2, c = idx & 3;
        uint32_t ad = tile_addr(r, c);
        cp16(sbase + SM_A_OFF + ad, &g_E8[i0 + r][c * 16]);
        cp16(sbase + SM_B_OFF + ad, &g_E8[j0 + r][c * 16]);
    }
    if (tid < 32)       cp16(sbase + SM_HI_OFF + tid * 16, &g_h[i0 + tid * 4]);
    else if (tid < 64)  cp16(sbase + SM_HJ_OFF + (tid - 32) * 16, &g_h[j0 + (tid - 32) * 4]);
}

// ---------------- kernel 2: persistent fp8 Gram, 3-stage pipeline ---------
__global__ void __launch_bounds__(256, 2) gram_mma_kernel(float* __restrict__ out) {
    extern __shared__ __align__(16) char dyn[];
    __shared__ unsigned int s_last;
    __shared__ float sh_red[256];

    const int tid  = threadIdx.x;
    const int wid  = tid >> 5;
    const int lane = tid & 31;
    const int wrow = (wid & 3) * 32;
    const int wcol = (wid >> 2) * 64;
    const int g    = lane >> 2;        // 0..7
    const int q    = lane & 3;         // 0..3
    const uint32_t db = smem_u32(dyn);

    const int t_beg = blockIdx.x * CHUNK;
    const int t_end = min(t_beg + CHUNK, NPAIRS);

    if (t_beg < t_end) {
        int pr_cur = __ldg(&g_pair[t_beg]);
        prefetch_tile(db + 0 * STAGE_BYTES, pr_cur, tid);
        CP_COMMIT();
        int pr_n1 = 0;
        if (t_beg + 1 < t_end) {
            pr_n1 = __ldg(&g_pair[t_beg + 1]);
            prefetch_tile(db + 1 * STAGE_BYTES, pr_n1, tid);
            CP_COMMIT();
        }

        int s = 0;
        for (int t = t_beg; t < t_end; t++) {
            if (t + 1 < t_end) { CP_WAIT(1); } else { CP_WAIT(0); }
            __syncthreads();

            int pr_n2 = 0;
            if (t + 2 < t_end) {
                pr_n2 = __ldg(&g_pair[t + 2]);
                int ns = s + 2; if (ns >= 3) ns -= 3;
                prefetch_tile(db + ns * STAGE_BYTES, pr_n2, tid);
                CP_COMMIT();
            }

            const int ti = pr_cur >> 8, tj = pr_cur & 255;
            const int i0 = ti * 128, j0 = tj * 128;
            const bool offdiag = (tj > ti);
            const uint32_t sAb = db + s * STAGE_BYTES + SM_A_OFF;
            const uint32_t sBb = db + s * STAGE_BYTES + SM_B_OFF;
            const float* s_hi = reinterpret_cast<const float*>(dyn + s * STAGE_BYTES + SM_HI_OFF);
            const float* s_hj = reinterpret_cast<const float*>(dyn + s * STAGE_BYTES + SM_HJ_OFF);

            float hi[2][2];
#pragma unroll
            for (int mt = 0; mt < 2; mt++) {
                int r0 = wrow + mt * 16 + g;
                hi[mt][0] = s_hi[r0];
                hi[mt][1] = s_hi[r0 + 8];
            }

            float acc[2][8][4];
#pragma unroll
            for (int ks = 0; ks < 2; ks++) {       // K = 64, k32 per step
                const int cb = ks * 2;
                uint32_t a[2][4];
#pragma unroll
                for (int mt = 0; mt < 2; mt++) {
                    int r = wrow + mt * 16 + (lane & 15);
                    int c = cb + (lane >> 4);
                    ldsm_x4(a[mt], sAb + tile_addr(r, c));
                }
                uint32_t b[4][4];
#pragma unroll
                for (int np = 0; np < 4; np++) {
                    int grp = lane >> 3, r8 = lane & 7;
                    int r = wcol + np * 16 + ((grp >> 1) << 3) + r8;
                    int c = cb + (grp & 1);
                    ldsm_x4(b[np], sBb + tile_addr(r, c));
                }
                if (ks == 0) {
#pragma unroll
                    for (int mt = 0; mt < 2; mt++)
#pragma unroll
                        for (int np = 0; np < 4; np++) {
                            mma_fp8_zc(acc[mt][np * 2 + 0], a[mt], &b[np][0]);
                            mma_fp8_zc(acc[mt][np * 2 + 1], a[mt], &b[np][2]);
                        }
                } else {
#pragma unroll
                    for (int mt = 0; mt < 2; mt++)
#pragma unroll
                        for (int np = 0; np < 4; np++) {
                            mma_fp8(acc[mt][np * 2 + 0], a[mt], &b[np][0]);
                            mma_fp8(acc[mt][np * 2 + 1], a[mt], &b[np][2]);
                        }
                }
            }

            // pruning pass: exact args, warp max, no MUFU
            float wmax = -1e30f;
#pragma unroll
            for (int nt = 0; nt < 8; nt++) {
                int lc = wcol + nt * 8 + q * 2;
                float hj0 = s_hj[lc], hj1 = s_hj[lc + 1];
#pragma unroll
                for (int mt = 0; mt < 2; mt++) {
                    float m0 = fmaxf(acc[mt][nt][0] + (hi[mt][0] + hj0),
                                     acc[mt][nt][1] + (hi[mt][0] + hj1));
                    float m1 = fmaxf(acc[mt][nt][2] + (hi[mt][1] + hj0),
                                     acc[mt][nt][3] + (hi[mt][1] + hj1));
                    wmax = fmaxf(wmax, fmaxf(m0, m1));
                }
            }

            if (__any_sync(0xffffffffu, wmax > THRESH)) {
                float rs[4] = {0.0f, 0.0f, 0.0f, 0.0f};
#pragma unroll
                for (int nt = 0; nt < 8; nt++) {
                    int lc = wcol + nt * 8 + q * 2;
                    float hj0 = s_hj[lc], hj1 = s_hj[lc + 1];
                    float c0 = 0.0f, c1 = 0.0f;
#pragma unroll
                    for (int mt = 0; mt < 2; mt++) {
                        float e0 = __expf(fminf(acc[mt][nt][0] + hi[mt][0] + hj0, 0.0f));
                        float e1 = __expf(fminf(acc[mt][nt][1] + hi[mt][0] + hj1, 0.0f));
                        float e2 = __expf(fminf(acc[mt][nt][2] + hi[mt][1] + hj0, 0.0f));
                        float e3 = __expf(fminf(acc[mt][nt][3] + hi[mt][1] + hj1, 0.0f));
                        rs[mt * 2 + 0] += e0 + e1;
                        rs[mt * 2 + 1] += e2 + e3;
                        c0 += e0 + e2;
                        c1 += e1 + e3;
                    }
                    if (offdiag) {
                        c0 += __shfl_xor_sync(0xffffffffu, c0, 4);
                        c0 += __shfl_xor_sync(0xffffffffu, c0, 8);
                        c0 += __shfl_xor_sync(0xffffffffu, c0, 16);
                        c1 += __shfl_xor_sync(0xffffffffu, c1, 4);
                        c1 += __shfl_xor_sync(0xffffffffu, c1, 8);
                        c1 += __shfl_xor_sync(0xffffffffu, c1, 16);
                        if (g == nt) {
                            atomicAdd(&g_rowsum[j0 + lc], c0);
                            atomicAdd(&g_rowsum[j0 + lc + 1], c1);
                        }
                    }
                }
#pragma unroll
                for (int k = 0; k < 4; k++) {
                    rs[k] += __shfl_xor_sync(0xffffffffu, rs[k], 1);
                    rs[k] += __shfl_xor_sync(0xffffffffu, rs[k], 2);
                }
                int row = i0 + wrow + (q >> 1) * 16 + (q & 1) * 8 + g;
                atomicAdd(&g_rowsum[row], rs[q]);
            }

            pr_cur = pr_n1;
            pr_n1 = pr_n2;
            s++; if (s >= 3) s -= 3;
        }
    }

    // ---- last-CTA final reduction ----
    __threadfence();
    __syncthreads();
    if (tid == 0) {
        unsigned int old = atomicAdd(&g_ctr, 1u);
        s_last = (old == gridDim.x - 1) ? 1u : 0u;
        if (s_last) g_ctr = 0;   // reset for next graph replay
    }
    __syncthreads();
    if (s_last) {
        float s = 0.0f;
        for (int i = tid; i < NROWS; i += 256) s += logf(__ldcg(&g_rowsum[i]));
        float m = 0.0f;
        for (int i = tid; i < MSE_BLOCKS; i += 256) m += g_msep[i];
        sh_red[tid] = s;
        __syncthreads();
        for (int o = 128; o > 0; o >>= 1) {
            if (tid < o) sh_red[tid] += sh_red[tid + o];
            __syncthreads();
        }
        float stot = sh_red[0];
        __syncthreads();
        sh_red[tid] = m;
        __syncthreads();
        for (int o = 128; o > 0; o >>= 1) {
            if (tid < o) sh_red[tid] += sh_red[tid + o];
            __syncthreads();
        }
        if (tid == 0) {
            float kde  = stot / (float)NROWS;
            float IXT  = (logf((float)NROWS) - kde) * 1.44269504088896340736f;
            float dist = sh_red[0] / (float)(NROWS * DDIM);
            out[0] = IXT + 500.0f * dist;
            out[1] = IXT;
            out[2] = dist;
        }
    }
}

extern "C" void kernel_launch(void* const* d_in, const int* in_sizes, int n_in,
                              void* d_out, int out_size) {
    const float* y_true  = (const float*)d_in[0];
    const float* y_pred  = (const float*)d_in[1];
    const float* encoded = (const float*)d_in[2];
    float* out = (float*)d_out;

    static bool attr_done = false;
    if (!attr_done) {
        cudaFuncSetAttribute(gram_mma_kernel,
                             cudaFuncAttributeMaxDynamicSharedMemorySize, SM_DYN);
        attr_done = true;
    }

    prep_fused<<<32 + MSE_BLOCKS + LUT_BLOCKS, 256>>>(encoded, y_true, y_pred);
    gram_mma_kernel<<<GRID, 256, SM_DYN>>>(out);
}